// round 16
// baseline (speedup 1.0000x reference)
#include <cuda_runtime.h>
#include <cuda_bf16.h>

#define NN 100000
#define EE 1600000
#define FF 64

typedef unsigned long long u64t;

// Scratch: Tx1 only (t2 is consumed in-place by the fused pass 2).
__device__ __align__(16) float g_t1[NN * FF];
__device__ int g_rowptr[NN + 1];

// ---------------------------------------------------------------------------
// Kernel 1: CSR row pointers via binary search (rows is sorted).
// ---------------------------------------------------------------------------
__global__ void build_rowptr(const int* __restrict__ rows) {
    int i = blockIdx.x * blockDim.x + threadIdx.x;
    if (i > NN) return;
    int lo = 0, hi = EE;
    while (lo < hi) {
        int mid = (lo + hi) >> 1;
        if (rows[mid] < i) lo = mid + 1; else hi = mid;
    }
    g_rowptr[i] = lo;
}

// ---------------------------------------------------------------------------
// Helpers
// ---------------------------------------------------------------------------
__device__ __forceinline__ u64t shfl64(u64t v, int src) {
    return (u64t)__shfl_sync(0xffffffffu, (unsigned long long)v, src);
}

#define FMA2(ACC, W, D) \
    asm("fma.rn.f32x2 %0, %1, %2, %0;" : "+l"(ACC) : "l"(W), "l"(D))

__device__ __forceinline__ u64t pack2(float lo, float hi) {
    return (u64t)__float_as_uint(lo) | ((u64t)__float_as_uint(hi) << 32);
}

// Warp-level SPMM for one row: acc = sum_e vals[e] * src[cols[e]] (float2/lane).
__device__ __forceinline__ float2 gather_row(const float2* __restrict__ h2,
                                             const int* __restrict__ cols,
                                             const float* __restrict__ vals,
                                             int s, int e, int lane) {
    float accx = 0.f, accy = 0.f;
    int i = s;
    for (; i + 4 <= e; i += 4) {
        int   c0 = cols[i],  c1 = cols[i + 1], c2 = cols[i + 2], c3 = cols[i + 3];
        float v0 = vals[i],  v1 = vals[i + 1], v2 = vals[i + 2], v3 = vals[i + 3];
        float2 a = h2[c0 * 32 + lane];
        float2 b = h2[c1 * 32 + lane];
        float2 c = h2[c2 * 32 + lane];
        float2 d = h2[c3 * 32 + lane];
        accx += v0 * a.x; accy += v0 * a.y;
        accx += v1 * b.x; accy += v1 * b.y;
        accx += v2 * c.x; accy += v2 * c.y;
        accx += v3 * d.x; accy += v3 * d.y;
    }
    for (; i < e; ++i) {
        int   c = cols[i];
        float v = vals[i];
        float2 a = h2[c * 32 + lane];
        accx += v * a.x; accy += v * a.y;
    }
    return make_float2(accx, accy);
}

// Stage one 64x64 weight matrix in k-pair-packed layout:
// sW[m*32 + l] = { (W[2m][2l], W[2m+1][2l]) , (W[2m][2l+1], W[2m+1][2l+1]) }
// so .x multiplies col j0=2l and .y multiplies col j1=2l+1, both as (even-k,odd-k) packs.
__device__ __forceinline__ void stage_pack(ulonglong2* sW, float2 a, float2 b,
                                           int idx) {
    ulonglong2 p;
    p.x = pack2(a.x, b.x);
    p.y = pack2(a.y, b.y);
    sW[idx] = p;
}

// ---------------------------------------------------------------------------
// Fused pass 1: t1 = A@x (written to g_t1)  AND
//               out = x@(W0-W2) + t1@W1 + bias
// Warp handles 4 consecutive rows. Grid 3125 x 256 thr = exactly 100000 rows.
// ---------------------------------------------------------------------------
__global__ void __launch_bounds__(256)
fused_pass1(const float* __restrict__ x,
            const int* __restrict__ cols,
            const float* __restrict__ vals,
            const float* __restrict__ weight,
            const float* __restrict__ bias,
            float* __restrict__ out) {
    __shared__ __align__(16) ulonglong2 sW0[1024];  // W0 - W2 (operand: x)
    __shared__ __align__(16) ulonglong2 sW1[1024];  // W1      (operand: t1)

    const int tid = threadIdx.x;
    const int lane = tid & 31;

    // Stage packed weights. weight float2 view: kk stride 2048, row k stride 32.
    const float2* w2 = (const float2*)weight;
    for (int idx = tid; idx < 1024; idx += 256) {
        int m = idx >> 5, l = idx & 31;
        float2 a0 = w2[(2 * m) * 32 + l];
        float2 b0 = w2[(2 * m + 1) * 32 + l];
        float2 a2 = w2[4096 + (2 * m) * 32 + l];
        float2 b2 = w2[4096 + (2 * m + 1) * 32 + l];
        stage_pack(sW0, make_float2(a0.x - a2.x, a0.y - a2.y),
                        make_float2(b0.x - b2.x, b0.y - b2.y), idx);
        float2 a1 = w2[2048 + (2 * m) * 32 + l];
        float2 b1 = w2[2048 + (2 * m + 1) * 32 + l];
        stage_pack(sW1, a1, b1, idx);
    }
    __syncthreads();

    const int row0 = blockIdx.x * 32 + (tid >> 5) * 4;
    const float2* x2 = (const float2*)x;
    float2* t1out = (float2*)g_t1;

    // SPMM phase: 4 rows per warp.
    float2 t[4], xv[4];
#pragma unroll
    for (int r = 0; r < 4; ++r) {
        int row = row0 + r;
        int s = g_rowptr[row], e = g_rowptr[row + 1];
        t[r]  = gather_row(x2, cols, vals, s, e, lane);
        xv[r] = x2[row * 32 + lane];
        t1out[row * 32 + lane] = t[r];
    }

    // Fused GEMM: o[r][c] accumulates (even-k sum, odd-k sum) for col 2l+c.
    u64t o[4][2];
#pragma unroll
    for (int r = 0; r < 4; ++r) { o[r][0] = 0ull; o[r][1] = 0ull; }

    u64t txv[4], ttv[4];
#pragma unroll
    for (int r = 0; r < 4; ++r) {
        txv[r] = pack2(xv[r].x, xv[r].y);
        ttv[r] = pack2(t[r].x, t[r].y);
    }

#pragma unroll 8
    for (int m = 0; m < 32; ++m) {
        ulonglong2 w0 = sW0[m * 32 + lane];
        ulonglong2 w1 = sW1[m * 32 + lane];
#pragma unroll
        for (int r = 0; r < 4; ++r) {
            u64t tx = shfl64(txv[r], m);   // (x[2m], x[2m+1]) of row r
            u64t tt = shfl64(ttv[r], m);   // (t1[2m], t1[2m+1]) of row r
            FMA2(o[r][0], w0.x, tx);
            FMA2(o[r][1], w0.y, tx);
            FMA2(o[r][0], w1.x, tt);
            FMA2(o[r][1], w1.y, tt);
        }
    }

    // Epilogue: horizontal add + bias, store float2 (cols 2l, 2l+1).
    float2 bb = ((const float2*)bias)[lane];
    float2* out2 = (float2*)out;
#pragma unroll
    for (int r = 0; r < 4; ++r) {
        float e0, o0, e1, o1;
        asm("mov.b64 {%0, %1}, %2;" : "=f"(e0), "=f"(o0) : "l"(o[r][0]));
        asm("mov.b64 {%0, %1}, %2;" : "=f"(e1), "=f"(o1) : "l"(o[r][1]));
        out2[(row0 + r) * 32 + lane] =
            make_float2(e0 + o0 + bb.x, e1 + o1 + bb.y);
    }
}

// ---------------------------------------------------------------------------
// Fused pass 2: t2raw = A@t1 (kept in registers)  AND  out += t2raw @ (2*W2)
// ---------------------------------------------------------------------------
__global__ void __launch_bounds__(256)
fused_pass2(const int* __restrict__ cols,
            const float* __restrict__ vals,
            const float* __restrict__ weight,
            float* __restrict__ out) {
    __shared__ __align__(16) ulonglong2 sW2[1024];  // 2*W2 (operand: t2raw)

    const int tid = threadIdx.x;
    const int lane = tid & 31;

    const float2* w2 = (const float2*)weight;
    for (int idx = tid; idx < 1024; idx += 256) {
        int m = idx >> 5, l = idx & 31;
        float2 a = w2[4096 + (2 * m) * 32 + l];
        float2 b = w2[4096 + (2 * m + 1) * 32 + l];
        stage_pack(sW2, make_float2(2.f * a.x, 2.f * a.y),
                        make_float2(2.f * b.x, 2.f * b.y), idx);
    }
    __syncthreads();

    const int row0 = blockIdx.x * 32 + (tid >> 5) * 4;
    const float2* t1in = (const float2*)g_t1;

    float2 t[4];
#pragma unroll
    for (int r = 0; r < 4; ++r) {
        int row = row0 + r;
        int s = g_rowptr[row], e = g_rowptr[row + 1];
        t[r] = gather_row(t1in, cols, vals, s, e, lane);
    }

    u64t o[4][2];
#pragma unroll
    for (int r = 0; r < 4; ++r) { o[r][0] = 0ull; o[r][1] = 0ull; }

    u64t ttv[4];
#pragma unroll
    for (int r = 0; r < 4; ++r) ttv[r] = pack2(t[r].x, t[r].y);

#pragma unroll 8
    for (int m = 0; m < 32; ++m) {
        ulonglong2 w = sW2[m * 32 + lane];
#pragma unroll
        for (int r = 0; r < 4; ++r) {
            u64t tt = shfl64(ttv[r], m);
            FMA2(o[r][0], w.x, tt);
            FMA2(o[r][1], w.y, tt);
        }
    }

    float2* out2 = (float2*)out;
#pragma unroll
    for (int r = 0; r < 4; ++r) {
        float e0, o0, e1, o1;
        asm("mov.b64 {%0, %1}, %2;" : "=f"(e0), "=f"(o0) : "l"(o[r][0]));
        asm("mov.b64 {%0, %1}, %2;" : "=f"(e1), "=f"(o1) : "l"(o[r][1]));
        float2 prev = out2[(row0 + r) * 32 + lane];
        out2[(row0 + r) * 32 + lane] =
            make_float2(prev.x + e0 + o0, prev.y + e1 + o1);
    }
}

// ---------------------------------------------------------------------------
extern "C" void kernel_launch(void* const* d_in, const int* in_sizes, int n_in,
                              void* d_out, int out_size) {
    const float* x      = (const float*)d_in[0];
    const int*   rows   = (const int*)d_in[1];
    const int*   cols   = (const int*)d_in[2];
    const float* vals   = (const float*)d_in[3];
    const float* weight = (const float*)d_in[4];
    const float* bias   = (const float*)d_in[5];
    float*       out    = (float*)d_out;

    build_rowptr<<<(NN + 1 + 255) / 256, 256>>>(rows);
    fused_pass1<<<NN / 32, 256>>>(x, cols, vals, weight, bias, out);
    fused_pass2<<<NN / 32, 256>>>(cols, vals, weight, out);
}

// round 17
// speedup vs baseline: 1.0034x; 1.0034x over previous
#include <cuda_runtime.h>
#include <cuda_bf16.h>

#define NN 100000
#define EE 1600000
#define FF 64

typedef unsigned long long u64t;

// Scratch: Tx1 only (t2 is consumed in-place by the fused pass 2).
__device__ __align__(16) float g_t1[NN * FF];
__device__ int g_rowptr[NN + 1];

// ---------------------------------------------------------------------------
// Kernel 1: CSR row pointers via binary search (rows is sorted).
// ---------------------------------------------------------------------------
__global__ void build_rowptr(const int* __restrict__ rows) {
    int i = blockIdx.x * blockDim.x + threadIdx.x;
    if (i > NN) return;
    int lo = 0, hi = EE;
    while (lo < hi) {
        int mid = (lo + hi) >> 1;
        if (rows[mid] < i) lo = mid + 1; else hi = mid;
    }
    g_rowptr[i] = lo;
}

// ---------------------------------------------------------------------------
// Helpers
// ---------------------------------------------------------------------------
__device__ __forceinline__ u64t shfl64(u64t v, int src) {
    return (u64t)__shfl_sync(0xffffffffu, (unsigned long long)v, src);
}

#define FMA2(ACC, W, D) \
    asm("fma.rn.f32x2 %0, %1, %2, %0;" : "+l"(ACC) : "l"(W), "l"(D))

__device__ __forceinline__ u64t pack2(float lo, float hi) {
    return (u64t)__float_as_uint(lo) | ((u64t)__float_as_uint(hi) << 32);
}

// Warp-level SPMM for one row: acc = sum_e vals[e] * src[cols[e]] (float2/lane).
__device__ __forceinline__ float2 gather_row(const float2* __restrict__ h2,
                                             const int* __restrict__ cols,
                                             const float* __restrict__ vals,
                                             int s, int e, int lane) {
    float accx = 0.f, accy = 0.f;
    int i = s;
    for (; i + 4 <= e; i += 4) {
        int   c0 = cols[i],  c1 = cols[i + 1], c2 = cols[i + 2], c3 = cols[i + 3];
        float v0 = vals[i],  v1 = vals[i + 1], v2 = vals[i + 2], v3 = vals[i + 3];
        float2 a = h2[c0 * 32 + lane];
        float2 b = h2[c1 * 32 + lane];
        float2 c = h2[c2 * 32 + lane];
        float2 d = h2[c3 * 32 + lane];
        accx += v0 * a.x; accy += v0 * a.y;
        accx += v1 * b.x; accy += v1 * b.y;
        accx += v2 * c.x; accy += v2 * c.y;
        accx += v3 * d.x; accy += v3 * d.y;
    }
    for (; i < e; ++i) {
        int   c = cols[i];
        float v = vals[i];
        float2 a = h2[c * 32 + lane];
        accx += v * a.x; accy += v * a.y;
    }
    return make_float2(accx, accy);
}

// Stage one 64x64 weight matrix in k-pair-packed layout:
// sW[m*32 + l] = { (W[2m][2l], W[2m+1][2l]) , (W[2m][2l+1], W[2m+1][2l+1]) }
// so .x multiplies col j0=2l and .y multiplies col j1=2l+1, both as (even-k,odd-k) packs.
__device__ __forceinline__ void stage_pack(ulonglong2* sW, float2 a, float2 b,
                                           int idx) {
    ulonglong2 p;
    p.x = pack2(a.x, b.x);
    p.y = pack2(a.y, b.y);
    sW[idx] = p;
}

// ---------------------------------------------------------------------------
// Fused pass 1: t1 = A@x (written to g_t1)  AND
//               out = x@(W0-W2) + t1@W1 + bias
// Warp handles 4 consecutive rows. Grid 3125 x 256 thr = exactly 100000 rows.
// ---------------------------------------------------------------------------
__global__ void __launch_bounds__(256)
fused_pass1(const float* __restrict__ x,
            const int* __restrict__ cols,
            const float* __restrict__ vals,
            const float* __restrict__ weight,
            const float* __restrict__ bias,
            float* __restrict__ out) {
    __shared__ __align__(16) ulonglong2 sW0[1024];  // W0 - W2 (operand: x)
    __shared__ __align__(16) ulonglong2 sW1[1024];  // W1      (operand: t1)

    const int tid = threadIdx.x;
    const int lane = tid & 31;

    // Stage packed weights. weight float2 view: kk stride 2048, row k stride 32.
    const float2* w2 = (const float2*)weight;
    for (int idx = tid; idx < 1024; idx += 256) {
        int m = idx >> 5, l = idx & 31;
        float2 a0 = w2[(2 * m) * 32 + l];
        float2 b0 = w2[(2 * m + 1) * 32 + l];
        float2 a2 = w2[4096 + (2 * m) * 32 + l];
        float2 b2 = w2[4096 + (2 * m + 1) * 32 + l];
        stage_pack(sW0, make_float2(a0.x - a2.x, a0.y - a2.y),
                        make_float2(b0.x - b2.x, b0.y - b2.y), idx);
        float2 a1 = w2[2048 + (2 * m) * 32 + l];
        float2 b1 = w2[2048 + (2 * m + 1) * 32 + l];
        stage_pack(sW1, a1, b1, idx);
    }
    __syncthreads();

    const int row0 = blockIdx.x * 32 + (tid >> 5) * 4;
    const float2* x2 = (const float2*)x;
    float2* t1out = (float2*)g_t1;

    // SPMM phase: 4 rows per warp.
    float2 t[4], xv[4];
#pragma unroll
    for (int r = 0; r < 4; ++r) {
        int row = row0 + r;
        int s = g_rowptr[row], e = g_rowptr[row + 1];
        t[r]  = gather_row(x2, cols, vals, s, e, lane);
        xv[r] = x2[row * 32 + lane];
        t1out[row * 32 + lane] = t[r];
    }

    // Fused GEMM: o[r][c] accumulates (even-k sum, odd-k sum) for col 2l+c.
    u64t o[4][2];
#pragma unroll
    for (int r = 0; r < 4; ++r) { o[r][0] = 0ull; o[r][1] = 0ull; }

    u64t txv[4], ttv[4];
#pragma unroll
    for (int r = 0; r < 4; ++r) {
        txv[r] = pack2(xv[r].x, xv[r].y);
        ttv[r] = pack2(t[r].x, t[r].y);
    }

#pragma unroll 8
    for (int m = 0; m < 32; ++m) {
        ulonglong2 w0 = sW0[m * 32 + lane];
        ulonglong2 w1 = sW1[m * 32 + lane];
#pragma unroll
        for (int r = 0; r < 4; ++r) {
            u64t tx = shfl64(txv[r], m);   // (x[2m], x[2m+1]) of row r
            u64t tt = shfl64(ttv[r], m);   // (t1[2m], t1[2m+1]) of row r
            FMA2(o[r][0], w0.x, tx);
            FMA2(o[r][1], w0.y, tx);
            FMA2(o[r][0], w1.x, tt);
            FMA2(o[r][1], w1.y, tt);
        }
    }

    // Epilogue: horizontal add + bias, store float2 (cols 2l, 2l+1).
    float2 bb = ((const float2*)bias)[lane];
    float2* out2 = (float2*)out;
#pragma unroll
    for (int r = 0; r < 4; ++r) {
        float e0, o0, e1, o1;
        asm("mov.b64 {%0, %1}, %2;" : "=f"(e0), "=f"(o0) : "l"(o[r][0]));
        asm("mov.b64 {%0, %1}, %2;" : "=f"(e1), "=f"(o1) : "l"(o[r][1]));
        out2[(row0 + r) * 32 + lane] =
            make_float2(e0 + o0 + bb.x, e1 + o1 + bb.y);
    }
}

// ---------------------------------------------------------------------------
// Fused pass 2: t2raw = A@t1 (kept in registers)  AND  out += t2raw @ (2*W2)
// ---------------------------------------------------------------------------
__global__ void __launch_bounds__(256)
fused_pass2(const int* __restrict__ cols,
            const float* __restrict__ vals,
            const float* __restrict__ weight,
            float* __restrict__ out) {
    __shared__ __align__(16) ulonglong2 sW2[1024];  // 2*W2 (operand: t2raw)

    const int tid = threadIdx.x;
    const int lane = tid & 31;

    const float2* w2 = (const float2*)weight;
    for (int idx = tid; idx < 1024; idx += 256) {
        int m = idx >> 5, l = idx & 31;
        float2 a = w2[4096 + (2 * m) * 32 + l];
        float2 b = w2[4096 + (2 * m + 1) * 32 + l];
        stage_pack(sW2, make_float2(2.f * a.x, 2.f * a.y),
                        make_float2(2.f * b.x, 2.f * b.y), idx);
    }
    __syncthreads();

    const int row0 = blockIdx.x * 32 + (tid >> 5) * 4;
    const float2* t1in = (const float2*)g_t1;

    float2 t[4];
#pragma unroll
    for (int r = 0; r < 4; ++r) {
        int row = row0 + r;
        int s = g_rowptr[row], e = g_rowptr[row + 1];
        t[r] = gather_row(t1in, cols, vals, s, e, lane);
    }

    u64t o[4][2];
#pragma unroll
    for (int r = 0; r < 4; ++r) { o[r][0] = 0ull; o[r][1] = 0ull; }

    u64t ttv[4];
#pragma unroll
    for (int r = 0; r < 4; ++r) ttv[r] = pack2(t[r].x, t[r].y);

#pragma unroll 8
    for (int m = 0; m < 32; ++m) {
        ulonglong2 w = sW2[m * 32 + lane];
#pragma unroll
        for (int r = 0; r < 4; ++r) {
            u64t tt = shfl64(ttv[r], m);
            FMA2(o[r][0], w.x, tt);
            FMA2(o[r][1], w.y, tt);
        }
    }

    float2* out2 = (float2*)out;
#pragma unroll
    for (int r = 0; r < 4; ++r) {
        float e0, o0, e1, o1;
        asm("mov.b64 {%0, %1}, %2;" : "=f"(e0), "=f"(o0) : "l"(o[r][0]));
        asm("mov.b64 {%0, %1}, %2;" : "=f"(e1), "=f"(o1) : "l"(o[r][1]));
        float2 prev = out2[(row0 + r) * 32 + lane];
        out2[(row0 + r) * 32 + lane] =
            make_float2(prev.x + e0 + o0, prev.y + e1 + o1);
    }
}

// ---------------------------------------------------------------------------
extern "C" void kernel_launch(void* const* d_in, const int* in_sizes, int n_in,
                              void* d_out, int out_size) {
    const float* x      = (const float*)d_in[0];
    const int*   rows   = (const int*)d_in[1];
    const int*   cols   = (const int*)d_in[2];
    const float* vals   = (const float*)d_in[3];
    const float* weight = (const float*)d_in[4];
    const float* bias   = (const float*)d_in[5];
    float*       out    = (float*)d_out;

    build_rowptr<<<(NN + 1 + 255) / 256, 256>>>(rows);
    fused_pass1<<<NN / 32, 256>>>(x, cols, vals, weight, bias, out);
    fused_pass2<<<NN / 32, 256>>>(cols, vals, weight, out);
}